// round 13
// baseline (speedup 1.0000x reference)
#include <cuda_runtime.h>
#include <cuda_fp16.h>
#include <math.h>
#include <stdint.h>

// Problem constants
static const int cB = 64;
static const int cM = 512;
static const int cD = 2048;
static const int cK = 32;
static const int cBM = cB * cM;          // 32768

// Scratch (device globals; no allocation allowed)
__device__ __half g_sbh[cBM * cK];       // sa * inv_norm fp16, [b,m,k]  (2 MB)
__device__ float  g_colsum_p[cB * 4 * cK];   // per-L-block colsum partials
__device__ float  g_nrmsq_p[cB * 16 * cK];   // per-agg-block nrmsq partials

// ---------------------------------------------------------------------------
// helpers
// ---------------------------------------------------------------------------
__device__ __forceinline__ uint32_t s2u(const void* p) {
    return (uint32_t)__cvta_generic_to_shared(p);
}
__device__ __forceinline__ void ldmx4(uint32_t* r, uint32_t a) {
    asm volatile("ldmatrix.sync.aligned.m8n8.x4.shared.b16 {%0,%1,%2,%3},[%4];"
        : "=r"(r[0]), "=r"(r[1]), "=r"(r[2]), "=r"(r[3]) : "r"(a));
}
__device__ __forceinline__ void ldmx4t(uint32_t* r, uint32_t a) {
    asm volatile("ldmatrix.sync.aligned.m8n8.x4.trans.shared.b16 {%0,%1,%2,%3},[%4];"
        : "=r"(r[0]), "=r"(r[1]), "=r"(r[2]), "=r"(r[3]) : "r"(a));
}
__device__ __forceinline__ void mma16816(float* c, const uint32_t* a,
                                         uint32_t b0, uint32_t b1) {
    asm volatile(
        "mma.sync.aligned.m16n8k16.row.col.f32.f16.f16.f32 "
        "{%0,%1,%2,%3},{%4,%5,%6,%7},{%8,%9},{%0,%1,%2,%3};"
        : "+f"(c[0]), "+f"(c[1]), "+f"(c[2]), "+f"(c[3])
        : "r"(a[0]), "r"(a[1]), "r"(a[2]), "r"(a[3]), "r"(b0), "r"(b1));
}

// convert 8 fp32 -> 8 fp16 packed in uint4
__device__ __forceinline__ void cvt8(float4 a, float4 b, uint4& H) {
    __half2 h0 = __floats2half2_rn(a.x, a.y);
    __half2 h1 = __floats2half2_rn(a.z, a.w);
    __half2 h2 = __floats2half2_rn(b.x, b.y);
    __half2 h3 = __floats2half2_rn(b.z, b.w);
    H = make_uint4(*reinterpret_cast<uint32_t*>(&h0),
                   *reinterpret_cast<uint32_t*>(&h1),
                   *reinterpret_cast<uint32_t*>(&h2),
                   *reinterpret_cast<uint32_t*>(&h3));
}

// ---------------------------------------------------------------------------
// Kernel L: logits = (x @ W^T)*inv_norm, softmax, sbh = fp16(sa*inv), colsum
// partials. fp16 mma.sync m16n8k16, SW-pipelined (next chunk in registers).
// Block 256 thr (8 warps), tile M=128 rows x K=32 clusters, D chunk 64.
// ---------------------------------------------------------------------------
__global__ __launch_bounds__(256) void logits_kernel(
    const float* __restrict__ x, const float* __restrict__ W)
{
    __shared__ __align__(16) __half As[128 * 64];   // swizzled, 16 KB
    __shared__ __align__(16) __half Ws[32 * 64];    // 4 KB
    __shared__ float rowsq[128];
    __shared__ float colsum_s[32];

    const int t = threadIdx.x, lane = t & 31, w = t >> 5;
    const int bm0 = blockIdx.x * 128;
    const int b   = bm0 >> 9;
    const int qtr = (bm0 >> 7) & 3;
    if (t < 32) colsum_s[t] = 0.0f;

    float C[4][4];
#pragma unroll
    for (int i = 0; i < 4; i++)
#pragma unroll
        for (int j = 0; j < 4; j++) C[i][j] = 0.0f;
    float psq[4] = {0.f, 0.f, 0.f, 0.f};

    const int ar = t >> 3;       // staging: row base (+32i), unit au
    const int au = t & 7;
    const int wr = t >> 3, wu = t & 7;
    const int amr = 16 * w + (lane & 15);                 // A ldmatrix row
    const int bnr = (lane & 7) + ((lane >> 4) << 3);      // B ldmatrix n base

    const float* xbase = x + (size_t)(bm0 + ar) * 2048 + au * 8;
    const float* wbase = W + (size_t)wr * 2048 + wu * 8;

    float4 rx[4][2], rw[2];

    // prologue: prefetch chunk 0 (+ sumsq)
#pragma unroll
    for (int i = 0; i < 4; i++) {
        const float4* p = (const float4*)(xbase + (size_t)i * 32 * 2048);
        rx[i][0] = __ldcs(p); rx[i][1] = __ldcs(p + 1);
        float4 f0 = rx[i][0], f1 = rx[i][1];
        psq[i] += f0.x*f0.x + f0.y*f0.y + f0.z*f0.z + f0.w*f0.w
                + f1.x*f1.x + f1.y*f1.y + f1.z*f1.z + f1.w*f1.w;
    }
    { const float4* p = (const float4*)wbase; rw[0] = p[0]; rw[1] = p[1]; }

    for (int c = 0; c < 32; c++) {
        // commit prefetched regs -> smem (fp16, swizzled)
#pragma unroll
        for (int i = 0; i < 4; i++) {
            int r = ar + 32 * i;
            uint4 H; cvt8(rx[i][0], rx[i][1], H);
            *(uint4*)&As[r * 64 + ((au ^ (r & 7)) << 3)] = H;
        }
        {
            uint4 H; cvt8(rw[0], rw[1], H);
            *(uint4*)&Ws[wr * 64 + ((wu ^ (wr & 7)) << 3)] = H;
        }
        __syncthreads();

        // issue next chunk's global loads (overlap with MMAs below)
        if (c < 31) {
            int d0 = (c + 1) * 64;
#pragma unroll
            for (int i = 0; i < 4; i++) {
                const float4* p = (const float4*)(xbase + (size_t)i * 32 * 2048 + d0);
                rx[i][0] = __ldcs(p); rx[i][1] = __ldcs(p + 1);
            }
            const float4* p = (const float4*)(wbase + d0);
            rw[0] = p[0]; rw[1] = p[1];
        }

#pragma unroll
        for (int kk = 0; kk < 64; kk += 16) {
            uint32_t a[4], bb[8];
            int u = (kk >> 3) + (lane >> 4);
            ldmx4(a, s2u(&As[amr * 64 + ((u ^ (amr & 7)) << 3)]));
            int ub = (kk >> 3) + ((lane >> 3) & 1);
#pragma unroll
            for (int half = 0; half < 2; half++) {
                int n = bnr + 16 * half;
                ldmx4(bb + 4 * half, s2u(&Ws[n * 64 + ((ub ^ (n & 7)) << 3)]));
            }
#pragma unroll
            for (int nt = 0; nt < 4; nt++)
                mma16816(C[nt], a, bb[2*nt], bb[2*nt+1]);
        }

        // accumulate sumsq of the freshly prefetched chunk (regs)
        if (c < 31) {
#pragma unroll
            for (int i = 0; i < 4; i++) {
                float4 f0 = rx[i][0], f1 = rx[i][1];
                psq[i] += f0.x*f0.x + f0.y*f0.y + f0.z*f0.z + f0.w*f0.w
                        + f1.x*f1.x + f1.y*f1.y + f1.z*f1.z + f1.w*f1.w;
            }
        }
        __syncthreads();
    }

    // reduce sumsq: 8 lanes (same t>>3 group) share each row
#pragma unroll
    for (int i = 0; i < 4; i++) {
        float v = psq[i];
        v += __shfl_xor_sync(0xFFFFFFFFu, v, 1);
        v += __shfl_xor_sync(0xFFFFFFFFu, v, 2);
        v += __shfl_xor_sync(0xFFFFFFFFu, v, 4);
        if ((lane & 7) == 0) rowsq[(t >> 3) + 32 * i] = v;
    }
    __syncthreads();

    // softmax epilogue: thread holds rows 16w+g and +8, cols 8nt+2q(+1)
    const int g = lane >> 2, q = lane & 3;
    float csv[8];
#pragma unroll
    for (int i = 0; i < 8; i++) csv[i] = 0.0f;

#pragma unroll
    for (int idx = 0; idx < 2; idx++) {
        int r = 16 * w + g + 8 * idx;
        float inv = 1.0f / fmaxf(sqrtf(rowsq[r]), 1e-12f);
        float v[8];
#pragma unroll
        for (int nt = 0; nt < 4; nt++) {
            v[2*nt]   = C[nt][2*idx]   * inv;
            v[2*nt+1] = C[nt][2*idx+1] * inv;
        }
        float mx = v[0];
#pragma unroll
        for (int i = 1; i < 8; i++) mx = fmaxf(mx, v[i]);
        mx = fmaxf(mx, __shfl_xor_sync(0xFFFFFFFFu, mx, 1));
        mx = fmaxf(mx, __shfl_xor_sync(0xFFFFFFFFu, mx, 2));
        float s = 0.0f;
#pragma unroll
        for (int i = 0; i < 8; i++) { v[i] = __expf(v[i] - mx); s += v[i]; }
        s += __shfl_xor_sync(0xFFFFFFFFu, s, 1);
        s += __shfl_xor_sync(0xFFFFFFFFu, s, 2);
        float is = 1.0f / s;
#pragma unroll
        for (int nt = 0; nt < 4; nt++) {
            float sa0 = v[2*nt] * is, sa1 = v[2*nt+1] * is;
            csv[2*nt] += sa0; csv[2*nt+1] += sa1;
            __half2 hv = __floats2half2_rn(sa0 * inv, sa1 * inv);
            *(__half2*)&g_sbh[(size_t)(bm0 + r) * 32 + 8*nt + 2*q] = hv;
        }
    }
    // colsum reduce over g-groups, then shared atomics, then partial slot
#pragma unroll
    for (int i = 0; i < 8; i++) {
        float v = csv[i];
        v += __shfl_xor_sync(0xFFFFFFFFu, v, 4);
        v += __shfl_xor_sync(0xFFFFFFFFu, v, 8);
        v += __shfl_xor_sync(0xFFFFFFFFu, v, 16);
        if (g == 0) atomicAdd(&colsum_s[8 * (i >> 1) + 2 * q + (i & 1)], v);
    }
    __syncthreads();
    if (t < 32) g_colsum_p[(b * 4 + qtr) * 32 + t] = colsum_s[t];
}

// ---------------------------------------------------------------------------
// Kernel G: agg[b] = sb[b]^T @ x[b], fp16, SW-pipelined.
// sb comes pre-converted (fp16) from g_sbh -> raw uint2 copy into Ss.
// Epilogue: vlad = agg - colsum*cent (colsum = sum of 4 partials),
// write out, write per-block nrmsq partial slot (no global atomics).
// ---------------------------------------------------------------------------
__global__ __launch_bounds__(256) void agg_kernel(
    const float* __restrict__ x, const float* __restrict__ cent,
    float* __restrict__ out)
{
    __shared__ __align__(16) __half Xs[64 * 128];   // [m][d] swizzled, 16 KB
    __shared__ __align__(16) __half Ss[64 * 56];    // [m][k], stride 56, 7 KB
    __shared__ float nsq_s[32];

    const int t = threadIdx.x, lane = t & 31, w = t >> 5;
    const int b  = blockIdx.x >> 4;
    const int dc = blockIdx.x & 15;
    const int d0 = dc * 128;
    if (t < 32) nsq_s[t] = 0.0f;

    float C[4][4];
#pragma unroll
    for (int i = 0; i < 4; i++)
#pragma unroll
        for (int j = 0; j < 4; j++) C[i][j] = 0.0f;

    const int xu = t & 15, xr0 = t >> 4;
    const int sm0 = t >> 3;                   // sb rows sm0, sm0+32 (0..63)
    const int skq = (t & 7) * 4;              // half-quad within row
    const int clb = 16 * (w & 1);
    const int dwb = 32 * (w >> 1);

    const float* xbase = x + (size_t)(b * 512 + xr0) * 2048 + d0 + xu * 8;
    const __half* sbase = g_sbh + (size_t)(b * 512 + sm0) * 32 + skq;

    float4 xr[4][2];
    uint2 sr[2];

    // prologue: prefetch chunk 0
#pragma unroll
    for (int i = 0; i < 4; i++) {
        const float4* p = (const float4*)(xbase + (size_t)i * 16 * 2048);
        xr[i][0] = __ldcs(p); xr[i][1] = __ldcs(p + 1);
    }
#pragma unroll
    for (int i = 0; i < 2; i++)
        sr[i] = *(const uint2*)(sbase + (size_t)i * 32 * 32);

    for (int c = 0; c < 8; c++) {
        // commit regs -> smem
#pragma unroll
        for (int i = 0; i < 4; i++) {
            int r = xr0 + 16 * i;
            uint4 H; cvt8(xr[i][0], xr[i][1], H);
            *(uint4*)&Xs[r * 128 + ((xu ^ (r & 7)) << 3)] = H;
        }
#pragma unroll
        for (int i = 0; i < 2; i++)
            *(uint2*)&Ss[(sm0 + 32 * i) * 56 + skq] = sr[i];
        __syncthreads();

        // issue next chunk's loads
        if (c < 7) {
            size_t moff = (size_t)(c + 1) * 64;
#pragma unroll
            for (int i = 0; i < 4; i++) {
                const float4* p = (const float4*)(xbase + (moff + i * 16) * 2048);
                xr[i][0] = __ldcs(p); xr[i][1] = __ldcs(p + 1);
            }
#pragma unroll
            for (int i = 0; i < 2; i++)
                sr[i] = *(const uint2*)(sbase + (moff + (size_t)i * 32) * 32);
        }

#pragma unroll
        for (int kk = 0; kk < 64; kk += 16) {
            uint32_t a[4], bb[8];
            {   // A fragments (trans): stored [tok][cl] -> eff [cl][tok]
                int tok = kk + (lane & 7) + ((lane >> 4) << 3);
                int cl  = clb + ((lane >> 3) & 1) * 8;
                ldmx4t(a, s2u(&Ss[tok * 56 + cl]));
            }
            {   // B fragments (trans): stored [tok][d] -> eff [d][tok]
                int tok = kk + (lane & 7) + ((lane >> 3) & 1) * 8;
#pragma unroll
                for (int half = 0; half < 2; half++) {
                    int du = (dwb >> 3) + 2 * half + (lane >> 4);
                    int off = tok * 128 + ((du ^ (tok & 7)) << 3);
                    ldmx4t(bb + 4 * half, s2u(&Xs[off]));
                }
            }
#pragma unroll
            for (int nt = 0; nt < 4; nt++)
                mma16816(C[nt], a, bb[2*nt], bb[2*nt+1]);
        }
        __syncthreads();
    }

    // epilogue
    const int g = lane >> 2, q = lane & 3;
#pragma unroll
    for (int idx = 0; idx < 2; idx++) {
        int kr = clb + g + 8 * idx;
        float csk = g_colsum_p[(b * 4 + 0) * 32 + kr]
                  + g_colsum_p[(b * 4 + 1) * 32 + kr]
                  + g_colsum_p[(b * 4 + 2) * 32 + kr]
                  + g_colsum_p[(b * 4 + 3) * 32 + kr];
        float ssq = 0.0f;
#pragma unroll
        for (int nt = 0; nt < 4; nt++) {
            int d = d0 + dwb + 8 * nt + 2 * q;
            float2 cv = *(const float2*)&cent[(size_t)kr * 2048 + d];
            float o0 = C[nt][2*idx]   - csk * cv.x;
            float o1 = C[nt][2*idx+1] - csk * cv.y;
            *(float2*)&out[((size_t)b * 32 + kr) * 2048 + d] = make_float2(o0, o1);
            ssq += o0 * o0 + o1 * o1;
        }
        ssq += __shfl_xor_sync(0xFFFFFFFFu, ssq, 1);
        ssq += __shfl_xor_sync(0xFFFFFFFFu, ssq, 2);
        if (q == 0) atomicAdd(&nsq_s[kr], ssq);
    }
    __syncthreads();
    if (t < 32) g_nrmsq_p[(b * 16 + dc) * 32 + t] = nsq_s[t];
}

// ---------------------------------------------------------------------------
// scale: fused factor computation (from 16 nrmsq partials) + in-place rescale.
// ---------------------------------------------------------------------------
__global__ __launch_bounds__(256) void scale_kernel(float* __restrict__ out) {
    __shared__ float fac[32];
    const int t = threadIdx.x;
    const int base = blockIdx.x * 1024;          // float4 index
    const int b = base >> 14;                    // 16384 f4 per batch

    if (t < 32) {
        float nsq = 0.0f;
#pragma unroll
        for (int j = 0; j < 16; j++)
            nsq += g_nrmsq_p[(b * 16 + j) * 32 + t];
        float n   = sqrtf(nsq);
        float dn  = fmaxf(n, 1e-12f);
        float r   = n / dn;
        float g2  = r * r;
#pragma unroll
        for (int o = 1; o < 32; o <<= 1) g2 += __shfl_xor_sync(0xFFFFFFFFu, g2, o);
        float g = sqrtf(g2);
        fac[t] = 1.0f / (dn * fmaxf(g, 1e-12f));
    }
    __syncthreads();

    float4* o4 = (float4*)out;
#pragma unroll
    for (int j = 0; j < 4; j++) {
        int i = base + t + 256 * j;
        float f = fac[(i >> 9) & 31];            // 512 f4 per (b,k)
        float4 v = o4[i];
        v.x *= f; v.y *= f; v.z *= f; v.w *= f;
        o4[i] = v;
    }
}

// ---------------------------------------------------------------------------
extern "C" void kernel_launch(void* const* d_in, const int* in_sizes, int n_in,
                              void* d_out, int out_size) {
    const float* x    = (const float*)d_in[0];
    const float* Wm   = (const float*)d_in[1];
    const float* cent = (const float*)d_in[2];
    float* out        = (float*)d_out;

    logits_kernel<<<cBM / 128, 256>>>(x, Wm);
    agg_kernel<<<cB * 16, 256>>>(x, cent, out);
    scale_kernel<<<1024, 256>>>(out);
}

// round 14
// speedup vs baseline: 1.3456x; 1.3456x over previous
#include <cuda_runtime.h>
#include <cuda_fp16.h>
#include <math.h>
#include <stdint.h>

// Problem constants
static const int cB = 64;
static const int cM = 512;
static const int cD = 2048;
static const int cK = 32;
static const int cBM = cB * cM;          // 32768

// Scratch (device globals; no allocation allowed)
__device__ __half g_sbh[cBM * cK];       // sa * inv_norm fp16, [b,m,k]  (2 MB)
__device__ float  g_colsum_p[cB * 4 * cK];   // per-L-block colsum partials
__device__ float  g_nrmsq_p[cB * 16 * cK];   // per-agg-block nrmsq partials

// ---------------------------------------------------------------------------
// helpers
// ---------------------------------------------------------------------------
__device__ __forceinline__ uint32_t s2u(const void* p) {
    return (uint32_t)__cvta_generic_to_shared(p);
}
__device__ __forceinline__ void ldmx4(uint32_t* r, uint32_t a) {
    asm volatile("ldmatrix.sync.aligned.m8n8.x4.shared.b16 {%0,%1,%2,%3},[%4];"
        : "=r"(r[0]), "=r"(r[1]), "=r"(r[2]), "=r"(r[3]) : "r"(a));
}
__device__ __forceinline__ void ldmx4t(uint32_t* r, uint32_t a) {
    asm volatile("ldmatrix.sync.aligned.m8n8.x4.trans.shared.b16 {%0,%1,%2,%3},[%4];"
        : "=r"(r[0]), "=r"(r[1]), "=r"(r[2]), "=r"(r[3]) : "r"(a));
}
__device__ __forceinline__ void mma16816(float* c, const uint32_t* a,
                                         uint32_t b0, uint32_t b1) {
    asm volatile(
        "mma.sync.aligned.m16n8k16.row.col.f32.f16.f16.f32 "
        "{%0,%1,%2,%3},{%4,%5,%6,%7},{%8,%9},{%0,%1,%2,%3};"
        : "+f"(c[0]), "+f"(c[1]), "+f"(c[2]), "+f"(c[3])
        : "r"(a[0]), "r"(a[1]), "r"(a[2]), "r"(a[3]), "r"(b0), "r"(b1));
}

// convert 8 fp32 -> 8 fp16 packed in uint4
__device__ __forceinline__ void cvt8(float4 a, float4 b, uint4& H) {
    __half2 h0 = __floats2half2_rn(a.x, a.y);
    __half2 h1 = __floats2half2_rn(a.z, a.w);
    __half2 h2 = __floats2half2_rn(b.x, b.y);
    __half2 h3 = __floats2half2_rn(b.z, b.w);
    H = make_uint4(*reinterpret_cast<uint32_t*>(&h0),
                   *reinterpret_cast<uint32_t*>(&h1),
                   *reinterpret_cast<uint32_t*>(&h2),
                   *reinterpret_cast<uint32_t*>(&h3));
}

// ---------------------------------------------------------------------------
// Kernel L: logits = (x @ W^T)*inv_norm, softmax, sbh = fp16(sa*inv), colsum
// partials. fp16 mma.sync m16n8k16, SW-pipelined (next chunk in registers).
// Block 256 thr (8 warps), tile M=128 rows x K=32 clusters, D chunk 64.
// ---------------------------------------------------------------------------
__global__ __launch_bounds__(256) void logits_kernel(
    const float* __restrict__ x, const float* __restrict__ W)
{
    __shared__ __align__(16) __half As[128 * 64];   // swizzled, 16 KB
    __shared__ __align__(16) __half Ws[32 * 64];    // 4 KB
    __shared__ float rowsq[128];
    __shared__ float colsum_s[32];

    const int t = threadIdx.x, lane = t & 31, w = t >> 5;
    const int bm0 = blockIdx.x * 128;
    const int b   = bm0 >> 9;
    const int qtr = (bm0 >> 7) & 3;
    if (t < 32) colsum_s[t] = 0.0f;

    float C[4][4];
#pragma unroll
    for (int i = 0; i < 4; i++)
#pragma unroll
        for (int j = 0; j < 4; j++) C[i][j] = 0.0f;
    float psq[4] = {0.f, 0.f, 0.f, 0.f};

    const int ar = t >> 3;       // staging: row base (+32i), unit au
    const int au = t & 7;
    const int wr = t >> 3, wu = t & 7;
    const int amr = 16 * w + (lane & 15);                 // A ldmatrix row
    const int bnr = (lane & 7) + ((lane >> 4) << 3);      // B ldmatrix n base

    const float* xbase = x + (size_t)(bm0 + ar) * 2048 + au * 8;
    const float* wbase = W + (size_t)wr * 2048 + wu * 8;

    float4 rx[4][2], rw[2];

    // prologue: prefetch chunk 0 (+ sumsq)
#pragma unroll
    for (int i = 0; i < 4; i++) {
        const float4* p = (const float4*)(xbase + (size_t)i * 32 * 2048);
        rx[i][0] = p[0]; rx[i][1] = p[1];
        float4 f0 = rx[i][0], f1 = rx[i][1];
        psq[i] += f0.x*f0.x + f0.y*f0.y + f0.z*f0.z + f0.w*f0.w
                + f1.x*f1.x + f1.y*f1.y + f1.z*f1.z + f1.w*f1.w;
    }
    { const float4* p = (const float4*)wbase; rw[0] = p[0]; rw[1] = p[1]; }

    for (int c = 0; c < 32; c++) {
        // commit prefetched regs -> smem (fp16, swizzled)
#pragma unroll
        for (int i = 0; i < 4; i++) {
            int r = ar + 32 * i;
            uint4 H; cvt8(rx[i][0], rx[i][1], H);
            *(uint4*)&As[r * 64 + ((au ^ (r & 7)) << 3)] = H;
        }
        {
            uint4 H; cvt8(rw[0], rw[1], H);
            *(uint4*)&Ws[wr * 64 + ((wu ^ (wr & 7)) << 3)] = H;
        }
        __syncthreads();

        // issue next chunk's global loads (overlap with MMAs below)
        if (c < 31) {
            int d0 = (c + 1) * 64;
#pragma unroll
            for (int i = 0; i < 4; i++) {
                const float4* p = (const float4*)(xbase + (size_t)i * 32 * 2048 + d0);
                rx[i][0] = p[0]; rx[i][1] = p[1];
            }
            const float4* p = (const float4*)(wbase + d0);
            rw[0] = p[0]; rw[1] = p[1];
        }

#pragma unroll
        for (int kk = 0; kk < 64; kk += 16) {
            uint32_t a[4], bb[8];
            int u = (kk >> 3) + (lane >> 4);
            ldmx4(a, s2u(&As[amr * 64 + ((u ^ (amr & 7)) << 3)]));
            int ub = (kk >> 3) + ((lane >> 3) & 1);
#pragma unroll
            for (int half = 0; half < 2; half++) {
                int n = bnr + 16 * half;
                ldmx4(bb + 4 * half, s2u(&Ws[n * 64 + ((ub ^ (n & 7)) << 3)]));
            }
#pragma unroll
            for (int nt = 0; nt < 4; nt++)
                mma16816(C[nt], a, bb[2*nt], bb[2*nt+1]);
        }

        // accumulate sumsq of the freshly prefetched chunk (regs)
        if (c < 31) {
#pragma unroll
            for (int i = 0; i < 4; i++) {
                float4 f0 = rx[i][0], f1 = rx[i][1];
                psq[i] += f0.x*f0.x + f0.y*f0.y + f0.z*f0.z + f0.w*f0.w
                        + f1.x*f1.x + f1.y*f1.y + f1.z*f1.z + f1.w*f1.w;
            }
        }
        __syncthreads();
    }

    // reduce sumsq: 8 lanes (same t>>3 group) share each row
#pragma unroll
    for (int i = 0; i < 4; i++) {
        float v = psq[i];
        v += __shfl_xor_sync(0xFFFFFFFFu, v, 1);
        v += __shfl_xor_sync(0xFFFFFFFFu, v, 2);
        v += __shfl_xor_sync(0xFFFFFFFFu, v, 4);
        if ((lane & 7) == 0) rowsq[(t >> 3) + 32 * i] = v;
    }
    __syncthreads();

    // softmax epilogue: thread holds rows 16w+g and +8, cols 8nt+2q(+1)
    const int g = lane >> 2, q = lane & 3;
    float csv[8];
#pragma unroll
    for (int i = 0; i < 8; i++) csv[i] = 0.0f;

#pragma unroll
    for (int idx = 0; idx < 2; idx++) {
        int r = 16 * w + g + 8 * idx;
        float inv = 1.0f / fmaxf(sqrtf(rowsq[r]), 1e-12f);
        float v[8];
#pragma unroll
        for (int nt = 0; nt < 4; nt++) {
            v[2*nt]   = C[nt][2*idx]   * inv;
            v[2*nt+1] = C[nt][2*idx+1] * inv;
        }
        float mx = v[0];
#pragma unroll
        for (int i = 1; i < 8; i++) mx = fmaxf(mx, v[i]);
        mx = fmaxf(mx, __shfl_xor_sync(0xFFFFFFFFu, mx, 1));
        mx = fmaxf(mx, __shfl_xor_sync(0xFFFFFFFFu, mx, 2));
        float s = 0.0f;
#pragma unroll
        for (int i = 0; i < 8; i++) { v[i] = __expf(v[i] - mx); s += v[i]; }
        s += __shfl_xor_sync(0xFFFFFFFFu, s, 1);
        s += __shfl_xor_sync(0xFFFFFFFFu, s, 2);
        float is = 1.0f / s;
#pragma unroll
        for (int nt = 0; nt < 4; nt++) {
            float sa0 = v[2*nt] * is, sa1 = v[2*nt+1] * is;
            csv[2*nt] += sa0; csv[2*nt+1] += sa1;
            __half2 hv = __floats2half2_rn(sa0 * inv, sa1 * inv);
            *(__half2*)&g_sbh[(size_t)(bm0 + r) * 32 + 8*nt + 2*q] = hv;
        }
    }
    // colsum reduce over g-groups, then shared atomics, then partial slot
#pragma unroll
    for (int i = 0; i < 8; i++) {
        float v = csv[i];
        v += __shfl_xor_sync(0xFFFFFFFFu, v, 4);
        v += __shfl_xor_sync(0xFFFFFFFFu, v, 8);
        v += __shfl_xor_sync(0xFFFFFFFFu, v, 16);
        if (g == 0) atomicAdd(&colsum_s[8 * (i >> 1) + 2 * q + (i & 1)], v);
    }
    __syncthreads();
    if (t < 32) g_colsum_p[(b * 4 + qtr) * 32 + t] = colsum_s[t];
}

// ---------------------------------------------------------------------------
// Kernel G: agg[b] = sb[b]^T @ x[b], fp16, SW-pipelined.
// sb comes pre-converted (fp16) from g_sbh -> raw uint2 copy into Ss.
// Epilogue: vlad = agg - colsum*cent (colsum = sum of 4 partials),
// write out, write per-block nrmsq partial slot (no global atomics).
// ---------------------------------------------------------------------------
__global__ __launch_bounds__(256) void agg_kernel(
    const float* __restrict__ x, const float* __restrict__ cent,
    float* __restrict__ out)
{
    __shared__ __align__(16) __half Xs[64 * 128];   // [m][d] swizzled, 16 KB
    __shared__ __align__(16) __half Ss[64 * 56];    // [m][k], stride 56, 7 KB
    __shared__ float nsq_s[32];

    const int t = threadIdx.x, lane = t & 31, w = t >> 5;
    const int b  = blockIdx.x >> 4;
    const int dc = blockIdx.x & 15;
    const int d0 = dc * 128;
    if (t < 32) nsq_s[t] = 0.0f;

    float C[4][4];
#pragma unroll
    for (int i = 0; i < 4; i++)
#pragma unroll
        for (int j = 0; j < 4; j++) C[i][j] = 0.0f;

    const int xu = t & 15, xr0 = t >> 4;
    const int sm0 = t >> 3;                   // sb rows sm0, sm0+32 (0..63)
    const int skq = (t & 7) * 4;              // half-quad within row
    const int clb = 16 * (w & 1);
    const int dwb = 32 * (w >> 1);

    const float* xbase = x + (size_t)(b * 512 + xr0) * 2048 + d0 + xu * 8;
    const __half* sbase = g_sbh + (size_t)(b * 512 + sm0) * 32 + skq;

    float4 xr[4][2];
    uint2 sr[2];

    // prologue: prefetch chunk 0
#pragma unroll
    for (int i = 0; i < 4; i++) {
        const float4* p = (const float4*)(xbase + (size_t)i * 16 * 2048);
        xr[i][0] = p[0]; xr[i][1] = p[1];
    }
#pragma unroll
    for (int i = 0; i < 2; i++)
        sr[i] = *(const uint2*)(sbase + (size_t)i * 32 * 32);

    for (int c = 0; c < 8; c++) {
        // commit regs -> smem
#pragma unroll
        for (int i = 0; i < 4; i++) {
            int r = xr0 + 16 * i;
            uint4 H; cvt8(xr[i][0], xr[i][1], H);
            *(uint4*)&Xs[r * 128 + ((xu ^ (r & 7)) << 3)] = H;
        }
#pragma unroll
        for (int i = 0; i < 2; i++)
            *(uint2*)&Ss[(sm0 + 32 * i) * 56 + skq] = sr[i];
        __syncthreads();

        // issue next chunk's loads
        if (c < 7) {
            size_t moff = (size_t)(c + 1) * 64;
#pragma unroll
            for (int i = 0; i < 4; i++) {
                const float4* p = (const float4*)(xbase + (moff + i * 16) * 2048);
                xr[i][0] = p[0]; xr[i][1] = p[1];
            }
#pragma unroll
            for (int i = 0; i < 2; i++)
                sr[i] = *(const uint2*)(sbase + (moff + (size_t)i * 32) * 32);
        }

#pragma unroll
        for (int kk = 0; kk < 64; kk += 16) {
            uint32_t a[4], bb[8];
            {   // A fragments (trans): stored [tok][cl] -> eff [cl][tok]
                int tok = kk + (lane & 7) + ((lane >> 4) << 3);
                int cl  = clb + ((lane >> 3) & 1) * 8;
                ldmx4t(a, s2u(&Ss[tok * 56 + cl]));
            }
            {   // B fragments (trans): stored [tok][d] -> eff [d][tok]
                int tok = kk + (lane & 7) + ((lane >> 3) & 1) * 8;
#pragma unroll
                for (int half = 0; half < 2; half++) {
                    int du = (dwb >> 3) + 2 * half + (lane >> 4);
                    int off = tok * 128 + ((du ^ (tok & 7)) << 3);
                    ldmx4t(bb + 4 * half, s2u(&Xs[off]));
                }
            }
#pragma unroll
            for (int nt = 0; nt < 4; nt++)
                mma16816(C[nt], a, bb[2*nt], bb[2*nt+1]);
        }
        __syncthreads();
    }

    // epilogue
    const int g = lane >> 2, q = lane & 3;
#pragma unroll
    for (int idx = 0; idx < 2; idx++) {
        int kr = clb + g + 8 * idx;
        float csk = g_colsum_p[(b * 4 + 0) * 32 + kr]
                  + g_colsum_p[(b * 4 + 1) * 32 + kr]
                  + g_colsum_p[(b * 4 + 2) * 32 + kr]
                  + g_colsum_p[(b * 4 + 3) * 32 + kr];
        float ssq = 0.0f;
#pragma unroll
        for (int nt = 0; nt < 4; nt++) {
            int d = d0 + dwb + 8 * nt + 2 * q;
            float2 cv = *(const float2*)&cent[(size_t)kr * 2048 + d];
            float o0 = C[nt][2*idx]   - csk * cv.x;
            float o1 = C[nt][2*idx+1] - csk * cv.y;
            *(float2*)&out[((size_t)b * 32 + kr) * 2048 + d] = make_float2(o0, o1);
            ssq += o0 * o0 + o1 * o1;
        }
        ssq += __shfl_xor_sync(0xFFFFFFFFu, ssq, 1);
        ssq += __shfl_xor_sync(0xFFFFFFFFu, ssq, 2);
        if (q == 0) atomicAdd(&nsq_s[kr], ssq);
    }
    __syncthreads();
    if (t < 32) g_nrmsq_p[(b * 16 + dc) * 32 + t] = nsq_s[t];
}

// ---------------------------------------------------------------------------
// scale: fused factor computation (from 16 nrmsq partials) + in-place rescale.
// ---------------------------------------------------------------------------
__global__ __launch_bounds__(256) void scale_kernel(float* __restrict__ out) {
    __shared__ float fac[32];
    const int t = threadIdx.x;
    const int base = blockIdx.x * 1024;          // float4 index
    const int b = base >> 14;                    // 16384 f4 per batch

    if (t < 32) {
        float nsq = 0.0f;
#pragma unroll
        for (int j = 0; j < 16; j++)
            nsq += g_nrmsq_p[(b * 16 + j) * 32 + t];
        float n   = sqrtf(nsq);
        float dn  = fmaxf(n, 1e-12f);
        float r   = n / dn;
        float g2  = r * r;
#pragma unroll
        for (int o = 1; o < 32; o <<= 1) g2 += __shfl_xor_sync(0xFFFFFFFFu, g2, o);
        float g = sqrtf(g2);
        fac[t] = 1.0f / (dn * fmaxf(g, 1e-12f));
    }
    __syncthreads();

    float4* o4 = (float4*)out;
#pragma unroll
    for (int j = 0; j < 4; j++) {
        int i = base + t + 256 * j;
        float f = fac[(i >> 9) & 31];            // 512 f4 per (b,k)
        float4 v = o4[i];
        v.x *= f; v.y *= f; v.z *= f; v.w *= f;
        o4[i] = v;
    }
}

// ---------------------------------------------------------------------------
extern "C" void kernel_launch(void* const* d_in, const int* in_sizes, int n_in,
                              void* d_out, int out_size) {
    const float* x    = (const float*)d_in[0];
    const float* Wm   = (const float*)d_in[1];
    const float* cent = (const float*)d_in[2];
    float* out        = (float*)d_out;

    logits_kernel<<<cBM / 128, 256>>>(x, Wm);
    agg_kernel<<<cB * 16, 256>>>(x, cent, out);
    scale_kernel<<<1024, 256>>>(out);
}

// round 15
// speedup vs baseline: 1.4147x; 1.0513x over previous
#include <cuda_runtime.h>
#include <cuda_fp16.h>
#include <math.h>
#include <stdint.h>

// Problem constants
static const int cB = 64;
static const int cM = 512;
static const int cD = 2048;
static const int cK = 32;
static const int cBM = cB * cM;          // 32768

// Scratch (device globals; no allocation allowed)
__device__ __half g_sbh[cBM * cK];       // sa * inv_norm fp16, [b,m,k]  (2 MB)
__device__ float  g_colsum_p[cB * 4 * cK];   // per-L-block colsum partials
__device__ float  g_nrmsq_p[cB * 16 * cK];   // per-agg-block nrmsq partials

// ---------------------------------------------------------------------------
// helpers
// ---------------------------------------------------------------------------
__device__ __forceinline__ uint32_t s2u(const void* p) {
    return (uint32_t)__cvta_generic_to_shared(p);
}
__device__ __forceinline__ void ldmx4(uint32_t* r, uint32_t a) {
    asm volatile("ldmatrix.sync.aligned.m8n8.x4.shared.b16 {%0,%1,%2,%3},[%4];"
        : "=r"(r[0]), "=r"(r[1]), "=r"(r[2]), "=r"(r[3]) : "r"(a));
}
__device__ __forceinline__ void ldmx4t(uint32_t* r, uint32_t a) {
    asm volatile("ldmatrix.sync.aligned.m8n8.x4.trans.shared.b16 {%0,%1,%2,%3},[%4];"
        : "=r"(r[0]), "=r"(r[1]), "=r"(r[2]), "=r"(r[3]) : "r"(a));
}
__device__ __forceinline__ void mma16816(float* c, const uint32_t* a,
                                         uint32_t b0, uint32_t b1) {
    asm volatile(
        "mma.sync.aligned.m16n8k16.row.col.f32.f16.f16.f32 "
        "{%0,%1,%2,%3},{%4,%5,%6,%7},{%8,%9},{%0,%1,%2,%3};"
        : "+f"(c[0]), "+f"(c[1]), "+f"(c[2]), "+f"(c[3])
        : "r"(a[0]), "r"(a[1]), "r"(a[2]), "r"(a[3]), "r"(b0), "r"(b1));
}

// convert 8 fp32 -> 8 fp16 packed in uint4
__device__ __forceinline__ void cvt8(float4 a, float4 b, uint4& H) {
    __half2 h0 = __floats2half2_rn(a.x, a.y);
    __half2 h1 = __floats2half2_rn(a.z, a.w);
    __half2 h2 = __floats2half2_rn(b.x, b.y);
    __half2 h3 = __floats2half2_rn(b.z, b.w);
    H = make_uint4(*reinterpret_cast<uint32_t*>(&h0),
                   *reinterpret_cast<uint32_t*>(&h1),
                   *reinterpret_cast<uint32_t*>(&h2),
                   *reinterpret_cast<uint32_t*>(&h3));
}

// ---------------------------------------------------------------------------
// Kernel L: logits = (x @ W^T)*inv_norm, softmax, sbh = fp16(sa*inv), colsum
// partials. fp16 mma.sync m16n8k16. Double-buffered smem, ONE barrier per
// chunk: STS(c+1 -> buf^1) + LDG(c+2 -> regs) overlap MMA(buf).
// Block 256 thr (8 warps), tile M=128 rows x K=32 clusters, D chunk 64.
// ---------------------------------------------------------------------------
__global__ __launch_bounds__(256) void logits_kernel(
    const float* __restrict__ x, const float* __restrict__ W)
{
    __shared__ __align__(16) __half As[2][128 * 64];  // 32 KB
    __shared__ __align__(16) __half Ws[2][32 * 64];   //  8 KB
    __shared__ float rowsq[128];
    __shared__ float colsum_s[32];

    const int t = threadIdx.x, lane = t & 31, w = t >> 5;
    const int bm0 = blockIdx.x * 128;
    const int b   = bm0 >> 9;
    const int qtr = (bm0 >> 7) & 3;
    if (t < 32) colsum_s[t] = 0.0f;

    float C[4][4];
#pragma unroll
    for (int i = 0; i < 4; i++)
#pragma unroll
        for (int j = 0; j < 4; j++) C[i][j] = 0.0f;
    float psq[4] = {0.f, 0.f, 0.f, 0.f};

    const int ar = t >> 3;       // staging: row base (+32i), unit au
    const int au = t & 7;
    const int wr = t >> 3, wu = t & 7;
    const int amr = 16 * w + (lane & 15);                 // A ldmatrix row
    const int bnr = (lane & 7) + ((lane >> 4) << 3);      // B ldmatrix n base

    const float* xbase = x + (size_t)(bm0 + ar) * 2048 + au * 8;
    const float* wbase = W + (size_t)wr * 2048 + wu * 8;

    const int aoffS = ar * 64 + ((au ^ (ar & 7)) << 3);   // staging offsets
    const int woffS = wr * 64 + ((wu ^ (wr & 7)) << 3);

    float4 rx[4][2], rw[2];

    // prologue: chunk 0 -> regs -> buf0 ; then prefetch chunk 1 -> regs
#pragma unroll
    for (int i = 0; i < 4; i++) {
        const float4* p = (const float4*)(xbase + (size_t)i * 32 * 2048);
        rx[i][0] = p[0]; rx[i][1] = p[1];
        float4 f0 = rx[i][0], f1 = rx[i][1];
        psq[i] += f0.x*f0.x + f0.y*f0.y + f0.z*f0.z + f0.w*f0.w
                + f1.x*f1.x + f1.y*f1.y + f1.z*f1.z + f1.w*f1.w;
        uint4 H; cvt8(rx[i][0], rx[i][1], H);
        *(uint4*)&As[0][aoffS + i * 32 * 64] = H;
    }
    {
        const float4* p = (const float4*)wbase;
        rw[0] = p[0]; rw[1] = p[1];
        uint4 H; cvt8(rw[0], rw[1], H);
        *(uint4*)&Ws[0][woffS] = H;
    }
    __syncthreads();
    {
#pragma unroll
        for (int i = 0; i < 4; i++) {
            const float4* p = (const float4*)(xbase + (size_t)i * 32 * 2048 + 64);
            rx[i][0] = p[0]; rx[i][1] = p[1];
        }
        const float4* p = (const float4*)(wbase + 64);
        rw[0] = p[0]; rw[1] = p[1];
    }

    for (int c = 0; c < 32; c++) {
        const int cur = c & 1, nxt = cur ^ 1;

        // stage chunk c+1 regs -> buf nxt (+ its psq), then issue LDG c+2
        if (c < 31) {
#pragma unroll
            for (int i = 0; i < 4; i++) {
                float4 f0 = rx[i][0], f1 = rx[i][1];
                psq[i] += f0.x*f0.x + f0.y*f0.y + f0.z*f0.z + f0.w*f0.w
                        + f1.x*f1.x + f1.y*f1.y + f1.z*f1.z + f1.w*f1.w;
                uint4 H; cvt8(rx[i][0], rx[i][1], H);
                *(uint4*)&As[nxt][aoffS + i * 32 * 64] = H;
            }
            uint4 H; cvt8(rw[0], rw[1], H);
            *(uint4*)&Ws[nxt][woffS] = H;
        }
        if (c < 30) {
            int d0 = (c + 2) * 64;
#pragma unroll
            for (int i = 0; i < 4; i++) {
                const float4* p = (const float4*)(xbase + (size_t)i * 32 * 2048 + d0);
                rx[i][0] = p[0]; rx[i][1] = p[1];
            }
            const float4* p = (const float4*)(wbase + d0);
            rw[0] = p[0]; rw[1] = p[1];
        }

        // MMAs from buf cur (overlaps the LDGs above)
#pragma unroll
        for (int kk = 0; kk < 64; kk += 16) {
            uint32_t a[4], bb[8];
            int u = (kk >> 3) + (lane >> 4);
            ldmx4(a, s2u(&As[cur][amr * 64 + ((u ^ (amr & 7)) << 3)]));
            int ub = (kk >> 3) + ((lane >> 3) & 1);
#pragma unroll
            for (int half = 0; half < 2; half++) {
                int n = bnr + 16 * half;
                ldmx4(bb + 4 * half, s2u(&Ws[cur][n * 64 + ((ub ^ (n & 7)) << 3)]));
            }
#pragma unroll
            for (int nt = 0; nt < 4; nt++)
                mma16816(C[nt], a, bb[2*nt], bb[2*nt+1]);
        }
        __syncthreads();
    }

    // reduce sumsq: 8 lanes (same t>>3 group) share each row
#pragma unroll
    for (int i = 0; i < 4; i++) {
        float v = psq[i];
        v += __shfl_xor_sync(0xFFFFFFFFu, v, 1);
        v += __shfl_xor_sync(0xFFFFFFFFu, v, 2);
        v += __shfl_xor_sync(0xFFFFFFFFu, v, 4);
        if ((lane & 7) == 0) rowsq[(t >> 3) + 32 * i] = v;
    }
    __syncthreads();

    // softmax epilogue: thread holds rows 16w+g and +8, cols 8nt+2q(+1)
    const int g = lane >> 2, q = lane & 3;
    float csv[8];
#pragma unroll
    for (int i = 0; i < 8; i++) csv[i] = 0.0f;

#pragma unroll
    for (int idx = 0; idx < 2; idx++) {
        int r = 16 * w + g + 8 * idx;
        float inv = 1.0f / fmaxf(sqrtf(rowsq[r]), 1e-12f);
        float v[8];
#pragma unroll
        for (int nt = 0; nt < 4; nt++) {
            v[2*nt]   = C[nt][2*idx]   * inv;
            v[2*nt+1] = C[nt][2*idx+1] * inv;
        }
        float mx = v[0];
#pragma unroll
        for (int i = 1; i < 8; i++) mx = fmaxf(mx, v[i]);
        mx = fmaxf(mx, __shfl_xor_sync(0xFFFFFFFFu, mx, 1));
        mx = fmaxf(mx, __shfl_xor_sync(0xFFFFFFFFu, mx, 2));
        float s = 0.0f;
#pragma unroll
        for (int i = 0; i < 8; i++) { v[i] = __expf(v[i] - mx); s += v[i]; }
        s += __shfl_xor_sync(0xFFFFFFFFu, s, 1);
        s += __shfl_xor_sync(0xFFFFFFFFu, s, 2);
        float is = 1.0f / s;
#pragma unroll
        for (int nt = 0; nt < 4; nt++) {
            float sa0 = v[2*nt] * is, sa1 = v[2*nt+1] * is;
            csv[2*nt] += sa0; csv[2*nt+1] += sa1;
            __half2 hv = __floats2half2_rn(sa0 * inv, sa1 * inv);
            *(__half2*)&g_sbh[(size_t)(bm0 + r) * 32 + 8*nt + 2*q] = hv;
        }
    }
    // colsum reduce over g-groups, then shared atomics, then partial slot
#pragma unroll
    for (int i = 0; i < 8; i++) {
        float v = csv[i];
        v += __shfl_xor_sync(0xFFFFFFFFu, v, 4);
        v += __shfl_xor_sync(0xFFFFFFFFu, v, 8);
        v += __shfl_xor_sync(0xFFFFFFFFu, v, 16);
        if (g == 0) atomicAdd(&colsum_s[8 * (i >> 1) + 2 * q + (i & 1)], v);
    }
    __syncthreads();
    if (t < 32) g_colsum_p[(b * 4 + qtr) * 32 + t] = colsum_s[t];
}

// ---------------------------------------------------------------------------
// Kernel G: agg[b] = sb[b]^T @ x[b], fp16, double-buffered, one bar/chunk.
// sb comes pre-converted (fp16) from g_sbh -> raw uint2 copy into Ss.
// Epilogue: vlad = agg - colsum*cent, write out, nrmsq partial slot.
// ---------------------------------------------------------------------------
__global__ __launch_bounds__(256) void agg_kernel(
    const float* __restrict__ x, const float* __restrict__ cent,
    float* __restrict__ out)
{
    __shared__ __align__(16) __half Xs[2][64 * 128];  // 32 KB
    __shared__ __align__(16) __half Ss[2][64 * 56];   // 14 KB
    __shared__ float nsq_s[32];

    const int t = threadIdx.x, lane = t & 31, w = t >> 5;
    const int b  = blockIdx.x >> 4;
    const int dc = blockIdx.x & 15;
    const int d0 = dc * 128;
    if (t < 32) nsq_s[t] = 0.0f;

    float C[4][4];
#pragma unroll
    for (int i = 0; i < 4; i++)
#pragma unroll
        for (int j = 0; j < 4; j++) C[i][j] = 0.0f;

    const int xu = t & 15, xr0 = t >> 4;
    const int sm0 = t >> 3;                   // sb rows sm0, sm0+32 (0..63)
    const int skq = (t & 7) * 4;              // half-quad within row
    const int clb = 16 * (w & 1);
    const int dwb = 32 * (w >> 1);

    const float* xbase = x + (size_t)(b * 512 + xr0) * 2048 + d0 + xu * 8;
    const __half* sbase = g_sbh + (size_t)(b * 512 + sm0) * 32 + skq;

    const int xoffS = xr0 * 128 + ((xu ^ (xr0 & 7)) << 3);

    float4 xr[4][2];
    uint2 sr[2];

    // prologue: chunk 0 -> regs -> buf0 ; prefetch chunk 1 -> regs
#pragma unroll
    for (int i = 0; i < 4; i++) {
        const float4* p = (const float4*)(xbase + (size_t)i * 16 * 2048);
        xr[i][0] = p[0]; xr[i][1] = p[1];
        uint4 H; cvt8(xr[i][0], xr[i][1], H);
        *(uint4*)&Xs[0][xoffS + i * 16 * 128] = H;
    }
#pragma unroll
    for (int i = 0; i < 2; i++) {
        sr[i] = *(const uint2*)(sbase + (size_t)i * 32 * 32);
        *(uint2*)&Ss[0][(sm0 + 32 * i) * 56 + skq] = sr[i];
    }
    __syncthreads();
    {
#pragma unroll
        for (int i = 0; i < 4; i++) {
            const float4* p = (const float4*)(xbase + (size_t)(64 + i * 16) * 2048);
            xr[i][0] = p[0]; xr[i][1] = p[1];
        }
#pragma unroll
        for (int i = 0; i < 2; i++)
            sr[i] = *(const uint2*)(sbase + (size_t)(64 + i * 32) * 32);
    }

    for (int c = 0; c < 8; c++) {
        const int cur = c & 1, nxt = cur ^ 1;

        // stage chunk c+1 regs -> buf nxt, then issue LDG c+2
        if (c < 7) {
#pragma unroll
            for (int i = 0; i < 4; i++) {
                uint4 H; cvt8(xr[i][0], xr[i][1], H);
                *(uint4*)&Xs[nxt][xoffS + i * 16 * 128] = H;
            }
#pragma unroll
            for (int i = 0; i < 2; i++)
                *(uint2*)&Ss[nxt][(sm0 + 32 * i) * 56 + skq] = sr[i];
        }
        if (c < 6) {
            size_t moff = (size_t)(c + 2) * 64;
#pragma unroll
            for (int i = 0; i < 4; i++) {
                const float4* p = (const float4*)(xbase + (moff + i * 16) * 2048);
                xr[i][0] = p[0]; xr[i][1] = p[1];
            }
#pragma unroll
            for (int i = 0; i < 2; i++)
                sr[i] = *(const uint2*)(sbase + (moff + (size_t)i * 32) * 32);
        }

#pragma unroll
        for (int kk = 0; kk < 64; kk += 16) {
            uint32_t a[4], bb[8];
            {   // A fragments (trans): stored [tok][cl] -> eff [cl][tok]
                int tok = kk + (lane & 7) + ((lane >> 4) << 3);
                int cl  = clb + ((lane >> 3) & 1) * 8;
                ldmx4t(a, s2u(&Ss[cur][tok * 56 + cl]));
            }
            {   // B fragments (trans): stored [tok][d] -> eff [d][tok]
                int tok = kk + (lane & 7) + ((lane >> 3) & 1) * 8;
#pragma unroll
                for (int half = 0; half < 2; half++) {
                    int du = (dwb >> 3) + 2 * half + (lane >> 4);
                    int off = tok * 128 + ((du ^ (tok & 7)) << 3);
                    ldmx4t(bb + 4 * half, s2u(&Xs[cur][off]));
                }
            }
#pragma unroll
            for (int nt = 0; nt < 4; nt++)
                mma16816(C[nt], a, bb[2*nt], bb[2*nt+1]);
        }
        __syncthreads();
    }

    // epilogue
    const int g = lane >> 2, q = lane & 3;
#pragma unroll
    for (int idx = 0; idx < 2; idx++) {
        int kr = clb + g + 8 * idx;
        float csk = g_colsum_p[(b * 4 + 0) * 32 + kr]
                  + g_colsum_p[(b * 4 + 1) * 32 + kr]
                  + g_colsum_p[(b * 4 + 2) * 32 + kr]
                  + g_colsum_p[(b * 4 + 3) * 32 + kr];
        float ssq = 0.0f;
#pragma unroll
        for (int nt = 0; nt < 4; nt++) {
            int d = d0 + dwb + 8 * nt + 2 * q;
            float2 cv = *(const float2*)&cent[(size_t)kr * 2048 + d];
            float o0 = C[nt][2*idx]   - csk * cv.x;
            float o1 = C[nt][2*idx+1] - csk * cv.y;
            *(float2*)&out[((size_t)b * 32 + kr) * 2048 + d] = make_float2(o0, o1);
            ssq += o0 * o0 + o1 * o1;
        }
        ssq += __shfl_xor_sync(0xFFFFFFFFu, ssq, 1);
        ssq += __shfl_xor_sync(0xFFFFFFFFu, ssq, 2);
        if (q == 0) atomicAdd(&nsq_s[kr], ssq);
    }
    __syncthreads();
    if (t < 32) g_nrmsq_p[(b * 16 + dc) * 32 + t] = nsq_s[t];
}

// ---------------------------------------------------------------------------
// scale: fused factor computation (from 16 nrmsq partials) + in-place rescale.
// ---------------------------------------------------------------------------
__global__ __launch_bounds__(256) void scale_kernel(float* __restrict__ out) {
    __shared__ float fac[32];
    const int t = threadIdx.x;
    const int base = blockIdx.x * 1024;          // float4 index
    const int b = base >> 14;                    // 16384 f4 per batch

    if (t < 32) {
        float nsq = 0.0f;
#pragma unroll
        for (int j = 0; j < 16; j++)
            nsq += g_nrmsq_p[(b * 16 + j) * 32 + t];
        float n   = sqrtf(nsq);
        float dn  = fmaxf(n, 1e-12f);
        float r   = n / dn;
        float g2  = r * r;
#pragma unroll
        for (int o = 1; o < 32; o <<= 1) g2 += __shfl_xor_sync(0xFFFFFFFFu, g2, o);
        float g = sqrtf(g2);
        fac[t] = 1.0f / (dn * fmaxf(g, 1e-12f));
    }
    __syncthreads();

    float4* o4 = (float4*)out;
#pragma unroll
    for (int j = 0; j < 4; j++) {
        int i = base + t + 256 * j;
        float f = fac[(i >> 9) & 31];            // 512 f4 per (b,k)
        float4 v = o4[i];
        v.x *= f; v.y *= f; v.z *= f; v.w *= f;
        o4[i] = v;
    }
}

// ---------------------------------------------------------------------------
extern "C" void kernel_launch(void* const* d_in, const int* in_sizes, int n_in,
                              void* d_out, int out_size) {
    const float* x    = (const float*)d_in[0];
    const float* Wm   = (const float*)d_in[1];
    const float* cent = (const float*)d_in[2];
    float* out        = (float*)d_out;

    logits_kernel<<<cBM / 128, 256>>>(x, Wm);
    agg_kernel<<<cB * 16, 256>>>(x, cent, out);
    scale_kernel<<<1024, 256>>>(out);
}

// round 16
// speedup vs baseline: 1.4183x; 1.0025x over previous
#include <cuda_runtime.h>
#include <cuda_fp16.h>
#include <math.h>
#include <stdint.h>

// Problem constants
static const int cB = 64;
static const int cM = 512;
static const int cD = 2048;
static const int cK = 32;
static const int cBM = cB * cM;          // 32768

// Scratch (device globals; no allocation allowed)
__device__ __half g_sbh[cBM * cK];       // sa * inv_norm fp16, [b,m,k]  (2 MB)
__device__ float  g_colsum_p[cB * 4 * cK];   // per-L-block colsum partials
__device__ float  g_nrmsq_p[cB * 16 * cK];   // per-agg-block nrmsq partials

// ---------------------------------------------------------------------------
// helpers
// ---------------------------------------------------------------------------
__device__ __forceinline__ uint32_t s2u(const void* p) {
    return (uint32_t)__cvta_generic_to_shared(p);
}
__device__ __forceinline__ void ldmx4(uint32_t* r, uint32_t a) {
    asm volatile("ldmatrix.sync.aligned.m8n8.x4.shared.b16 {%0,%1,%2,%3},[%4];"
        : "=r"(r[0]), "=r"(r[1]), "=r"(r[2]), "=r"(r[3]) : "r"(a));
}
__device__ __forceinline__ void ldmx4t(uint32_t* r, uint32_t a) {
    asm volatile("ldmatrix.sync.aligned.m8n8.x4.trans.shared.b16 {%0,%1,%2,%3},[%4];"
        : "=r"(r[0]), "=r"(r[1]), "=r"(r[2]), "=r"(r[3]) : "r"(a));
}
__device__ __forceinline__ void mma16816(float* c, const uint32_t* a,
                                         uint32_t b0, uint32_t b1) {
    asm volatile(
        "mma.sync.aligned.m16n8k16.row.col.f32.f16.f16.f32 "
        "{%0,%1,%2,%3},{%4,%5,%6,%7},{%8,%9},{%0,%1,%2,%3};"
        : "+f"(c[0]), "+f"(c[1]), "+f"(c[2]), "+f"(c[3])
        : "r"(a[0]), "r"(a[1]), "r"(a[2]), "r"(a[3]), "r"(b0), "r"(b1));
}

// convert 8 fp32 -> 8 fp16 packed in uint4
__device__ __forceinline__ void cvt8(float4 a, float4 b, uint4& H) {
    __half2 h0 = __floats2half2_rn(a.x, a.y);
    __half2 h1 = __floats2half2_rn(a.z, a.w);
    __half2 h2 = __floats2half2_rn(b.x, b.y);
    __half2 h3 = __floats2half2_rn(b.z, b.w);
    H = make_uint4(*reinterpret_cast<uint32_t*>(&h0),
                   *reinterpret_cast<uint32_t*>(&h1),
                   *reinterpret_cast<uint32_t*>(&h2),
                   *reinterpret_cast<uint32_t*>(&h3));
}

// ---------------------------------------------------------------------------
// Kernel L: logits = (x @ W^T)*inv_norm, softmax, sbh = fp16(sa*inv), colsum
// partials. fp16 mma.sync m16n8k16. Double-buffered smem, ONE barrier per
// chunk: STS(c+1 -> buf^1) + LDG(c+2 -> regs) overlap MMA(buf).
// Block 256 thr (8 warps), tile M=128 rows x K=32 clusters, D chunk 64.
// ---------------------------------------------------------------------------
__global__ __launch_bounds__(256) void logits_kernel(
    const float* __restrict__ x, const float* __restrict__ W)
{
    __shared__ __align__(16) __half As[2][128 * 64];  // 32 KB
    __shared__ __align__(16) __half Ws[2][32 * 64];   //  8 KB
    __shared__ float rowsq[128];
    __shared__ float colsum_s[32];

    const int t = threadIdx.x, lane = t & 31, w = t >> 5;
    const int bm0 = blockIdx.x * 128;
    const int b   = bm0 >> 9;
    const int qtr = (bm0 >> 7) & 3;
    if (t < 32) colsum_s[t] = 0.0f;

    float C[4][4];
#pragma unroll
    for (int i = 0; i < 4; i++)
#pragma unroll
        for (int j = 0; j < 4; j++) C[i][j] = 0.0f;
    float psq[4] = {0.f, 0.f, 0.f, 0.f};

    const int ar = t >> 3;       // staging: row base (+32i), unit au
    const int au = t & 7;
    const int wr = t >> 3, wu = t & 7;
    const int amr = 16 * w + (lane & 15);                 // A ldmatrix row
    const int bnr = (lane & 7) + ((lane >> 4) << 3);      // B ldmatrix n base

    const float* xbase = x + (size_t)(bm0 + ar) * 2048 + au * 8;
    const float* wbase = W + (size_t)wr * 2048 + wu * 8;

    const int aoffS = ar * 64 + ((au ^ (ar & 7)) << 3);   // staging offsets
    const int woffS = wr * 64 + ((wu ^ (wr & 7)) << 3);

    float4 rx[4][2], rw[2];

    // prologue: chunk 0 -> regs -> buf0 ; then prefetch chunk 1 -> regs
#pragma unroll
    for (int i = 0; i < 4; i++) {
        const float4* p = (const float4*)(xbase + (size_t)i * 32 * 2048);
        rx[i][0] = p[0]; rx[i][1] = p[1];
        float4 f0 = rx[i][0], f1 = rx[i][1];
        psq[i] += f0.x*f0.x + f0.y*f0.y + f0.z*f0.z + f0.w*f0.w
                + f1.x*f1.x + f1.y*f1.y + f1.z*f1.z + f1.w*f1.w;
        uint4 H; cvt8(rx[i][0], rx[i][1], H);
        *(uint4*)&As[0][aoffS + i * 32 * 64] = H;
    }
    {
        const float4* p = (const float4*)wbase;
        rw[0] = p[0]; rw[1] = p[1];
        uint4 H; cvt8(rw[0], rw[1], H);
        *(uint4*)&Ws[0][woffS] = H;
    }
    __syncthreads();
    {
#pragma unroll
        for (int i = 0; i < 4; i++) {
            const float4* p = (const float4*)(xbase + (size_t)i * 32 * 2048 + 64);
            rx[i][0] = p[0]; rx[i][1] = p[1];
        }
        const float4* p = (const float4*)(wbase + 64);
        rw[0] = p[0]; rw[1] = p[1];
    }

    for (int c = 0; c < 32; c++) {
        const int cur = c & 1, nxt = cur ^ 1;

        // stage chunk c+1 regs -> buf nxt (+ its psq), then issue LDG c+2
        if (c < 31) {
#pragma unroll
            for (int i = 0; i < 4; i++) {
                float4 f0 = rx[i][0], f1 = rx[i][1];
                psq[i] += f0.x*f0.x + f0.y*f0.y + f0.z*f0.z + f0.w*f0.w
                        + f1.x*f1.x + f1.y*f1.y + f1.z*f1.z + f1.w*f1.w;
                uint4 H; cvt8(rx[i][0], rx[i][1], H);
                *(uint4*)&As[nxt][aoffS + i * 32 * 64] = H;
            }
            uint4 H; cvt8(rw[0], rw[1], H);
            *(uint4*)&Ws[nxt][woffS] = H;
        }
        if (c < 30) {
            int d0 = (c + 2) * 64;
#pragma unroll
            for (int i = 0; i < 4; i++) {
                const float4* p = (const float4*)(xbase + (size_t)i * 32 * 2048 + d0);
                rx[i][0] = p[0]; rx[i][1] = p[1];
            }
            const float4* p = (const float4*)(wbase + d0);
            rw[0] = p[0]; rw[1] = p[1];
        }

        // MMAs from buf cur (overlaps the LDGs above)
#pragma unroll
        for (int kk = 0; kk < 64; kk += 16) {
            uint32_t a[4], bb[8];
            int u = (kk >> 3) + (lane >> 4);
            ldmx4(a, s2u(&As[cur][amr * 64 + ((u ^ (amr & 7)) << 3)]));
            int ub = (kk >> 3) + ((lane >> 3) & 1);
#pragma unroll
            for (int half = 0; half < 2; half++) {
                int n = bnr + 16 * half;
                ldmx4(bb + 4 * half, s2u(&Ws[cur][n * 64 + ((ub ^ (n & 7)) << 3)]));
            }
#pragma unroll
            for (int nt = 0; nt < 4; nt++)
                mma16816(C[nt], a, bb[2*nt], bb[2*nt+1]);
        }
        __syncthreads();
    }

    // reduce sumsq: 8 lanes (same t>>3 group) share each row
#pragma unroll
    for (int i = 0; i < 4; i++) {
        float v = psq[i];
        v += __shfl_xor_sync(0xFFFFFFFFu, v, 1);
        v += __shfl_xor_sync(0xFFFFFFFFu, v, 2);
        v += __shfl_xor_sync(0xFFFFFFFFu, v, 4);
        if ((lane & 7) == 0) rowsq[(t >> 3) + 32 * i] = v;
    }
    __syncthreads();

    // softmax epilogue: thread holds rows 16w+g and +8, cols 8nt+2q(+1)
    const int g = lane >> 2, q = lane & 3;
    float csv[8];
#pragma unroll
    for (int i = 0; i < 8; i++) csv[i] = 0.0f;

#pragma unroll
    for (int idx = 0; idx < 2; idx++) {
        int r = 16 * w + g + 8 * idx;
        float inv = 1.0f / fmaxf(sqrtf(rowsq[r]), 1e-12f);
        float v[8];
#pragma unroll
        for (int nt = 0; nt < 4; nt++) {
            v[2*nt]   = C[nt][2*idx]   * inv;
            v[2*nt+1] = C[nt][2*idx+1] * inv;
        }
        float mx = v[0];
#pragma unroll
        for (int i = 1; i < 8; i++) mx = fmaxf(mx, v[i]);
        mx = fmaxf(mx, __shfl_xor_sync(0xFFFFFFFFu, mx, 1));
        mx = fmaxf(mx, __shfl_xor_sync(0xFFFFFFFFu, mx, 2));
        float s = 0.0f;
#pragma unroll
        for (int i = 0; i < 8; i++) { v[i] = __expf(v[i] - mx); s += v[i]; }
        s += __shfl_xor_sync(0xFFFFFFFFu, s, 1);
        s += __shfl_xor_sync(0xFFFFFFFFu, s, 2);
        float is = 1.0f / s;
#pragma unroll
        for (int nt = 0; nt < 4; nt++) {
            float sa0 = v[2*nt] * is, sa1 = v[2*nt+1] * is;
            csv[2*nt] += sa0; csv[2*nt+1] += sa1;
            __half2 hv = __floats2half2_rn(sa0 * inv, sa1 * inv);
            *(__half2*)&g_sbh[(size_t)(bm0 + r) * 32 + 8*nt + 2*q] = hv;
        }
    }
    // colsum reduce over g-groups, then shared atomics, then partial slot
#pragma unroll
    for (int i = 0; i < 8; i++) {
        float v = csv[i];
        v += __shfl_xor_sync(0xFFFFFFFFu, v, 4);
        v += __shfl_xor_sync(0xFFFFFFFFu, v, 8);
        v += __shfl_xor_sync(0xFFFFFFFFu, v, 16);
        if (g == 0) atomicAdd(&colsum_s[8 * (i >> 1) + 2 * q + (i & 1)], v);
    }
    __syncthreads();
    if (t < 32) g_colsum_p[(b * 4 + qtr) * 32 + t] = colsum_s[t];
}

// ---------------------------------------------------------------------------
// Kernel G: agg[b] = sb[b]^T @ x[b], fp16, double-buffered, one bar/chunk.
// BATCH ORDER REVERSED: L streamed x in batch order 0->63, so L2 still holds
// the tail (~last 30 batches) when G starts. Reversed order makes G's first
// reads hit that residency; G's own tail (batch 0's out) then feeds the
// forward-ordered scale kernel L2-hot.
// ---------------------------------------------------------------------------
__global__ __launch_bounds__(256) void agg_kernel(
    const float* __restrict__ x, const float* __restrict__ cent,
    float* __restrict__ out)
{
    __shared__ __align__(16) __half Xs[2][64 * 128];  // 32 KB
    __shared__ __align__(16) __half Ss[2][64 * 56];   // 14 KB
    __shared__ float nsq_s[32];

    const int t = threadIdx.x, lane = t & 31, w = t >> 5;
    const int b  = 63 - (blockIdx.x >> 4);    // reversed batch order
    const int dc = blockIdx.x & 15;
    const int d0 = dc * 128;
    if (t < 32) nsq_s[t] = 0.0f;

    float C[4][4];
#pragma unroll
    for (int i = 0; i < 4; i++)
#pragma unroll
        for (int j = 0; j < 4; j++) C[i][j] = 0.0f;

    const int xu = t & 15, xr0 = t >> 4;
    const int sm0 = t >> 3;                   // sb rows sm0, sm0+32 (0..63)
    const int skq = (t & 7) * 4;              // half-quad within row
    const int clb = 16 * (w & 1);
    const int dwb = 32 * (w >> 1);

    const float* xbase = x + (size_t)(b * 512 + xr0) * 2048 + d0 + xu * 8;
    const __half* sbase = g_sbh + (size_t)(b * 512 + sm0) * 32 + skq;

    const int xoffS = xr0 * 128 + ((xu ^ (xr0 & 7)) << 3);

    float4 xr[4][2];
    uint2 sr[2];

    // prologue: chunk 0 -> regs -> buf0 ; prefetch chunk 1 -> regs
#pragma unroll
    for (int i = 0; i < 4; i++) {
        const float4* p = (const float4*)(xbase + (size_t)i * 16 * 2048);
        xr[i][0] = p[0]; xr[i][1] = p[1];
        uint4 H; cvt8(xr[i][0], xr[i][1], H);
        *(uint4*)&Xs[0][xoffS + i * 16 * 128] = H;
    }
#pragma unroll
    for (int i = 0; i < 2; i++) {
        sr[i] = *(const uint2*)(sbase + (size_t)i * 32 * 32);
        *(uint2*)&Ss[0][(sm0 + 32 * i) * 56 + skq] = sr[i];
    }
    __syncthreads();
    {
#pragma unroll
        for (int i = 0; i < 4; i++) {
            const float4* p = (const float4*)(xbase + (size_t)(64 + i * 16) * 2048);
            xr[i][0] = p[0]; xr[i][1] = p[1];
        }
#pragma unroll
        for (int i = 0; i < 2; i++)
            sr[i] = *(const uint2*)(sbase + (size_t)(64 + i * 32) * 32);
    }

    for (int c = 0; c < 8; c++) {
        const int cur = c & 1, nxt = cur ^ 1;

        // stage chunk c+1 regs -> buf nxt, then issue LDG c+2
        if (c < 7) {
#pragma unroll
            for (int i = 0; i < 4; i++) {
                uint4 H; cvt8(xr[i][0], xr[i][1], H);
                *(uint4*)&Xs[nxt][xoffS + i * 16 * 128] = H;
            }
#pragma unroll
            for (int i = 0; i < 2; i++)
                *(uint2*)&Ss[nxt][(sm0 + 32 * i) * 56 + skq] = sr[i];
        }
        if (c < 6) {
            size_t moff = (size_t)(c + 2) * 64;
#pragma unroll
            for (int i = 0; i < 4; i++) {
                const float4* p = (const float4*)(xbase + (moff + i * 16) * 2048);
                xr[i][0] = p[0]; xr[i][1] = p[1];
            }
#pragma unroll
            for (int i = 0; i < 2; i++)
                sr[i] = *(const uint2*)(sbase + (moff + (size_t)i * 32) * 32);
        }

#pragma unroll
        for (int kk = 0; kk < 64; kk += 16) {
            uint32_t a[4], bb[8];
            {   // A fragments (trans): stored [tok][cl] -> eff [cl][tok]
                int tok = kk + (lane & 7) + ((lane >> 4) << 3);
                int cl  = clb + ((lane >> 3) & 1) * 8;
                ldmx4t(a, s2u(&Ss[cur][tok * 56 + cl]));
            }
            {   // B fragments (trans): stored [tok][d] -> eff [d][tok]
                int tok = kk + (lane & 7) + ((lane >> 3) & 1) * 8;
#pragma unroll
                for (int half = 0; half < 2; half++) {
                    int du = (dwb >> 3) + 2 * half + (lane >> 4);
                    int off = tok * 128 + ((du ^ (tok & 7)) << 3);
                    ldmx4t(bb + 4 * half, s2u(&Xs[cur][off]));
                }
            }
#pragma unroll
            for (int nt = 0; nt < 4; nt++)
                mma16816(C[nt], a, bb[2*nt], bb[2*nt+1]);
        }
        __syncthreads();
    }

    // epilogue
    const int g = lane >> 2, q = lane & 3;
#pragma unroll
    for (int idx = 0; idx < 2; idx++) {
        int kr = clb + g + 8 * idx;
        float csk = g_colsum_p[(b * 4 + 0) * 32 + kr]
                  + g_colsum_p[(b * 4 + 1) * 32 + kr]
                  + g_colsum_p[(b * 4 + 2) * 32 + kr]
                  + g_colsum_p[(b * 4 + 3) * 32 + kr];
        float ssq = 0.0f;
#pragma unroll
        for (int nt = 0; nt < 4; nt++) {
            int d = d0 + dwb + 8 * nt + 2 * q;
            float2 cv = *(const float2*)&cent[(size_t)kr * 2048 + d];
            float o0 = C[nt][2*idx]   - csk * cv.x;
            float o1 = C[nt][2*idx+1] - csk * cv.y;
            *(float2*)&out[((size_t)b * 32 + kr) * 2048 + d] = make_float2(o0, o1);
            ssq += o0 * o0 + o1 * o1;
        }
        ssq += __shfl_xor_sync(0xFFFFFFFFu, ssq, 1);
        ssq += __shfl_xor_sync(0xFFFFFFFFu, ssq, 2);
        if (q == 0) atomicAdd(&nsq_s[kr], ssq);
    }
    __syncthreads();
    if (t < 32) g_nrmsq_p[(b * 16 + dc) * 32 + t] = nsq_s[t];
}

// ---------------------------------------------------------------------------
// scale: fused factor computation (from 16 nrmsq partials) + in-place rescale.
// Forward batch order — aligns with reversed agg's tail (batch 0 written last,
// read first here, L2-hot).
// ---------------------------------------------------------------------------
__global__ __launch_bounds__(256) void scale_kernel(float* __restrict__ out) {
    __shared__ float fac[32];
    const int t = threadIdx.x;
    const int base = blockIdx.x * 1024;          // float4 index
    const int b = base >> 14;                    // 16384 f4 per batch

    if (t < 32) {
        float nsq = 0.0f;
#pragma unroll
        for (int j = 0; j < 16; j++)
            nsq += g_nrmsq_p[(b * 16 + j) * 32 + t];
        float n   = sqrtf(nsq);
        float dn  = fmaxf(n, 1e-12f);
        float r   = n / dn;
        float g2  = r * r;
#pragma unroll
        for (int o = 1; o < 32; o <<= 1) g2 += __shfl_xor_sync(0xFFFFFFFFu, g2, o);
        float g = sqrtf(g2);
        fac[t] = 1.0f / (dn * fmaxf(g, 1e-12f));
    }
    __syncthreads();

    float4* o4 = (float4*)out;
#pragma unroll
    for (int j = 0; j < 4; j++) {
        int i = base + t + 256 * j;
        float f = fac[(i >> 9) & 31];            // 512 f4 per (b,k)
        float4 v = o4[i];
        v.x *= f; v.y *= f; v.z *= f; v.w *= f;
        o4[i] = v;
    }
}

// ---------------------------------------------------------------------------
extern "C" void kernel_launch(void* const* d_in, const int* in_sizes, int n_in,
                              void* d_out, int out_size) {
    const float* x    = (const float*)d_in[0];
    const float* Wm   = (const float*)d_in[1];
    const float* cent = (const float*)d_in[2];
    float* out        = (float*)d_out;

    logits_kernel<<<cBM / 128, 256>>>(x, Wm);
    agg_kernel<<<cB * 16, 256>>>(x, cent, out);
    scale_kernel<<<1024, 256>>>(out);
}